// round 16
// baseline (speedup 1.0000x reference)
#include <cuda_runtime.h>
#include <cuda_fp16.h>
#include <cstdint>

#define T_TOKENS 4096
#define DM 1024
#define DH 4096
#define NE 8

// ---------------- scratch (device globals) -----------------------------------
__device__ int   g_cnt[NE];
__device__ int   g_base[NE];
__device__ float g_probsum[NE];
__device__ int   g_idx[NE * T_TOKENS];
__device__ int   g_tok_e[T_TOKENS * 2];
__device__ int   g_tok_slot[T_TOKENS * 2];
__device__ float g_tok_w[T_TOKENS * 2];
__device__ __half g_xh[(size_t)T_TOKENS * DM];
__device__ __half g_Hh[(size_t)2 * T_TOKENS * DH];
__device__ float  g_Y[(size_t)2 * T_TOKENS * DM];
__device__ uint4  g_w12t[(size_t)NE * 32 * 64 * 512];
__device__ uint2  g_wot[(size_t)NE * 8 * 256 * 512];
// persistent-queue state
__device__ int g_tiles_in[6144];
__device__ int g_tiles_out[2048];
__device__ int g_ntiles_in, g_ntiles_out;
__device__ int g_tick_in, g_tick_out;
__device__ int g_ready;
__device__ int g_w12_ready[NE * 32];

// ---------------- helpers -----------------------------------------------------
__device__ __forceinline__ uint32_t smem_u32(const void* p) {
    uint32_t a;
    asm("{ .reg .u64 t; cvta.to.shared.u64 t, %1; cvt.u32.u64 %0, t; }" : "=r"(a) : "l"(p));
    return a;
}
__device__ __forceinline__ uint32_t pk(float lo, float hi) {
    __half2 h = __floats2half2_rn(lo, hi);
    return *(uint32_t*)&h;
}
__device__ __forceinline__ void cp16(uint32_t dst, const void* src) {
    asm volatile("cp.async.cg.shared.global [%0], [%1], 16;" :: "r"(dst), "l"(src) : "memory");
}
__device__ __forceinline__ void cp_commit() {
    asm volatile("cp.async.commit_group;" ::: "memory");
}
__device__ __forceinline__ void cp_wait3() {
    asm volatile("cp.async.wait_group 3;" ::: "memory");
}
__device__ __forceinline__ void ldm4(uint32_t a[4], uint32_t addr) {
    asm volatile("ldmatrix.sync.aligned.m8n8.x4.shared.b16 {%0,%1,%2,%3}, [%4];"
                 : "=r"(a[0]), "=r"(a[1]), "=r"(a[2]), "=r"(a[3]) : "r"(addr));
}
__device__ __forceinline__ void mma16(float c[4], const uint32_t a[4],
                                      uint32_t b0, uint32_t b1) {
    asm volatile("mma.sync.aligned.m16n8k16.row.col.f32.f16.f16.f32 "
                 "{%0,%1,%2,%3}, {%4,%5,%6,%7}, {%8,%9}, {%0,%1,%2,%3};"
                 : "+f"(c[0]), "+f"(c[1]), "+f"(c[2]), "+f"(c[3])
                 : "r"(a[0]), "r"(a[1]), "r"(a[2]), "r"(a[3]), "r"(b0), "r"(b1));
}

// ---------------- init --------------------------------------------------------
__global__ __launch_bounds__(256) void init_kernel() {
    int i = threadIdx.x;
    if (i < NE) { g_cnt[i] = 0; g_probsum[i] = 0.0f; }
    if (i == 0) { g_tick_in = 0; g_tick_out = 0; g_ready = 0; }
    if (i < NE * 32) g_w12_ready[i] = 0;
}

// ---------------- fused router + x fp16 conversion ----------------------------
__global__ __launch_bounds__(256) void router_prep(
    const float* __restrict__ x, const float* __restrict__ rw, const float* __restrict__ rb)
{
    __shared__ float s_rwT[NE * DM];
    const int tid = threadIdx.x;
    for (int i = tid; i < NE * DM; i += 256) {
        int k = i >> 3, e = i & 7;
        s_rwT[e * DM + k] = rw[i];
    }
    __syncthreads();

    const int lane = tid & 31, wid = tid >> 5;
    const int t = blockIdx.x * 8 + wid;
    const float4* xr = (const float4*)(x + (size_t)t * DM);

    float acc[NE];
#pragma unroll
    for (int e = 0; e < NE; e++) acc[e] = 0.0f;

#pragma unroll
    for (int it = 0; it < 8; it++) {
        const int k4 = it * 32 + lane;
        float4 v = xr[k4];
        uint2 o;
        o.x = pk(v.x, v.y);
        o.y = pk(v.z, v.w);
        *(uint2*)(g_xh + (size_t)t * DM + k4 * 4) = o;
#pragma unroll
        for (int e = 0; e < NE; e++) {
            float4 r = *(const float4*)(s_rwT + e * DM + k4 * 4);
            acc[e] += v.x * r.x + v.y * r.y + v.z * r.z + v.w * r.w;
        }
    }
#pragma unroll
    for (int e = 0; e < NE; e++)
#pragma unroll
        for (int off = 16; off > 0; off >>= 1)
            acc[e] += __shfl_xor_sync(0xffffffffu, acc[e], off);

    if (lane == 0) {
        float l[NE], p[NE];
        float m = -1e30f;
#pragma unroll
        for (int e = 0; e < NE; e++) { l[e] = acc[e] + rb[e]; m = fmaxf(m, l[e]); }
        float s = 0.0f;
#pragma unroll
        for (int e = 0; e < NE; e++) { p[e] = expf(l[e] - m); s += p[e]; }
        float inv = 1.0f / s;
#pragma unroll
        for (int e = 0; e < NE; e++) { p[e] *= inv; atomicAdd(&g_probsum[e], p[e]); }
        int i1 = 0; float p1 = p[0];
        int i2 = -1; float p2 = -1.0f;
#pragma unroll
        for (int e = 1; e < NE; e++) {
            if (p[e] > p1) { p2 = p1; i2 = i1; p1 = p[e]; i1 = e; }
            else if (p[e] > p2) { p2 = p[e]; i2 = e; }
        }
        int s1 = atomicAdd(&g_cnt[i1], 1);
        g_idx[i1 * T_TOKENS + s1] = t;
        int s2 = atomicAdd(&g_cnt[i2], 1);
        g_idx[i2 * T_TOKENS + s2] = t;
        g_tok_e[2 * t + 0] = i1; g_tok_slot[2 * t + 0] = s1; g_tok_w[2 * t + 0] = p1;
        g_tok_e[2 * t + 1] = i2; g_tok_slot[2 * t + 1] = s2; g_tok_w[2 * t + 1] = p2;
    }
}

// ---------------- FFN-in (persistent; GEMM + w12-prep + wo-prep items) ---------
#define FI_STAGE 21504
#define FI_NS 5
#define FI_B 5120
#define FI_TOK (FI_NS * FI_STAGE)
#define FI_BB1 (FI_TOK + 256)
#define FI_BB2 (FI_BB1 + 512)
#define FI_TILE (FI_BB2 + 512)
#define FI_SMEM (FI_TILE + 160)

__global__ __launch_bounds__(256, 2) void ffn_in_h(
    const float* __restrict__ b1, const float* __restrict__ b2,
    const float* __restrict__ w1, const float* __restrict__ w2,
    const float* __restrict__ wo, float* __restrict__ out)
{
    extern __shared__ __align__(16) char smem[];
    const uint32_t sb = smem_u32(smem);
    const int tid = threadIdx.x;
    const int lane = tid & 31, wid = tid >> 5;
    const int wm = (wid & 1) * 32, wn = (wid >> 1) * 32;
    const int g = lane >> 2, tg = lane & 3;
    const uint32_t lrow = lane & 15, lhalf = lane >> 4;
    int* s_tile = (int*)(smem + FI_TILE);
    int* toks = (int*)(smem + FI_TOK);
    float* bb1 = (float*)(smem + FI_BB1);
    float* bb2 = (float*)(smem + FI_BB2);
    float* s1c = (float*)smem;                 // 16x132 f32
    float* s2c = (float*)(smem + 8448);        // 16x132 f32

    // ---- finalize phase: CTA0 builds scan + tile lists ----
    bool ready_seen = false;
    if (blockIdx.x == 0) {
        int* s_rb = s_tile + 2;
        int* s_ti = s_rb + NE;
        int* s_to = s_ti + NE + 1;
        if (tid == 0) {
            int base = 0, ti = 0, to = 0;
            float lb = 0.0f;
            for (int e = 0; e < NE; e++) {
                g_base[e] = base;
                base += g_cnt[e];
                lb += ((float)g_cnt[e] / T_TOKENS) * (g_probsum[e] / T_TOKENS);
                int rb = (g_cnt[e] + 63) >> 6;
                s_rb[e] = rb;
                s_ti[e] = ti; s_to[e] = to;
                ti += rb * 32;
                to += rb * 8;
            }
            s_ti[NE] = ti; s_to[NE] = to;
            g_ntiles_in = ti; g_ntiles_out = to;
            out[(size_t)T_TOKENS * DM] = 0.01f * (float)NE * lb;
        }
        __syncthreads();
        const int nti = s_ti[NE], nto = s_to[NE];
        for (int i = tid; i < nti; i += 256) {
            int e = 0;
            while (i >= s_ti[e + 1]) e++;
            int loc = i - s_ti[e];
            int rb = s_rb[e];
            int nblk = loc / rb, r = loc - nblk * rb;
            g_tiles_in[i] = (e << 16) | (nblk << 8) | r;
        }
        for (int i = tid; i < nto; i += 256) {
            int e = 0;
            while (i >= s_to[e + 1]) e++;
            int loc = i - s_to[e];
            int rb = s_rb[e];
            int nblk = loc / rb, r = loc - nblk * rb;
            g_tiles_out[i] = (e << 16) | (nblk << 8) | r;
        }
        __syncthreads();
        if (tid == 0) {
            __threadfence();
            atomicExch(&g_ready, 1);
        }
        ready_seen = true;
    }

    // ---- persistent loop --------------------------------------------------
    // slots [0,512): w12 idx t
    // slots [512,2240): groups of 9: 8 w12 + 1 GEMM (w12 512..2047, GEMM 0..191)
    // slots [2240,8384): groups of 3: 2 GEMM + 1 wo (GEMM 192..4287, wo 0..2047)
    // slots >= 8384: GEMM idx t-4096
    while (true) {
        if (tid == 0) *s_tile = atomicAdd(&g_tick_in, 1);
        __syncthreads();
        const int t = *s_tile;
        int type, idx;   // 0=GEMM 1=w12 2=wo
        if (t < 512) { type = 1; idx = t; }
        else if (t < 2240) {
            int u = t - 512, grp = u / 9, r = u - grp * 9;
            if (r < 8) { type = 1; idx = 512 + grp * 8 + r; }
            else       { type = 0; idx = grp; }
        } else if (t < 8384) {
            int v = t - 2240, grp = v / 3, r = v - grp * 3;
            if (r == 2) { type = 2; idx = grp; }
            else        { type = 0; idx = 192 + grp * 2 + r; }
        } else { type = 0; idx = t - 4096; }

        if (type == 1) {
            // w12-prep: e = idx>>8, nblk = (idx>>3)&31, kb group = (idx&7)*8
            const int e = idx >> 8;
            const int nblk = (idx >> 3) & 31;
            const int kb0 = (idx & 7) * 8;
#pragma unroll 1
            for (int j = 0; j < 8; j++) {
                const int kb = kb0 + j;
                const float* w1e = w1 + (size_t)e * DM * DH + (size_t)(kb * 16) * DH + nblk * 128;
                const float* w2e = w2 + (size_t)e * DM * DH + (size_t)(kb * 16) * DH + nblk * 128;
#pragma unroll
                for (int r = 0; r < 2; r++) {
                    int t2 = tid + r * 256;
                    int k = t2 >> 5, n4 = (t2 & 31) * 4;
                    float4 v = *(const float4*)(w1e + (size_t)k * DH + n4);
                    s1c[k * 132 + n4] = v.x; s1c[k * 132 + n4 + 1] = v.y;
                    s1c[k * 132 + n4 + 2] = v.z; s1c[k * 132 + n4 + 3] = v.w;
                    v = *(const float4*)(w2e + (size_t)k * DH + n4);
                    s2c[k * 132 + n4] = v.x; s2c[k * 132 + n4 + 1] = v.y;
                    s2c[k * 132 + n4 + 2] = v.z; s2c[k * 132 + n4 + 3] = v.w;
                }
                __syncthreads();
                uint4* dst = g_w12t + ((size_t)((e * 32 + nblk) * 64 + kb)) * 512;
#pragma unroll
                for (int r = 0; r < 2; r++) {
                    int slot = tid + r * 256;
                    int ln = slot & 31, jn8 = slot >> 5;
                    int col = jn8 * 8 + (ln >> 2);
                    int k2 = (ln & 3) * 2;
                    uint4 o;
                    o.x = pk(s1c[k2 * 132 + col], s1c[(k2 + 1) * 132 + col]);
                    o.y = pk(s1c[(k2 + 8) * 132 + col], s1c[(k2 + 9) * 132 + col]);
                    o.z = pk(s2c[k2 * 132 + col], s2c[(k2 + 1) * 132 + col]);
                    o.w = pk(s2c[(k2 + 8) * 132 + col], s2c[(k2 + 9) * 132 + col]);
                    dst[slot] = o;
                }
                __syncthreads();
            }
            if (tid == 0) {
                __threadfence();
                atomicAdd(&g_w12_ready[e * 32 + nblk], 1);
            }
            continue;
        }

        if (type == 2) {
            // wo-prep: e = idx>>8, nblk = (idx>>5)&7, kb group = (idx&31)*8
            const int e = idx >> 8;
            const int nblk = (idx >> 5) & 7;
            const int kb0 = (idx & 31) * 8;
#pragma unroll 1
            for (int j = 0; j < 8; j++) {
                const int kb = kb0 + j;
                const float* we = wo + (size_t)e * DH * DM + (size_t)(kb * 16) * DM + nblk * 128;
#pragma unroll
                for (int r = 0; r < 2; r++) {
                    int t2 = tid + r * 256;
                    int k = t2 >> 5, n4 = (t2 & 31) * 4;
                    float4 v = *(const float4*)(we + (size_t)k * DM + n4);
                    s1c[k * 132 + n4] = v.x; s1c[k * 132 + n4 + 1] = v.y;
                    s1c[k * 132 + n4 + 2] = v.z; s1c[k * 132 + n4 + 3] = v.w;
                }
                __syncthreads();
                uint2* dst = g_wot + ((size_t)((e * 8 + nblk) * 256 + kb)) * 512;
#pragma unroll
                for (int r = 0; r < 2; r++) {
                    int slot = tid + r * 256;
                    int ln = slot & 31, jn8 = slot >> 5;
                    int col = jn8 * 8 + (ln >> 2);
                    int k2 = (ln & 3) * 2;
                    uint2 o;
                    o.x = pk(s1c[k2 * 132 + col], s1c[(k2 + 1) * 132 + col]);
                    o.y = pk(s1c[(k2 + 8) * 132 + col], s1c[(k2 + 9) * 132 + col]);
                    dst[slot] = o;
                }
                __syncthreads();
            }
            continue;
        }

        // ---- GEMM tile ----
        if (!ready_seen) {
            if (tid == 0) {
                while (atomicAdd(&g_ready, 0) == 0) { }
            }
            __syncthreads();
            ready_seen = true;
        }
        if (idx >= g_ntiles_in) {
            if (t >= 8384) break;
            continue;
        }
        const int w = g_tiles_in[idx];
        const int e = w >> 16, nblk = (w >> 8) & 255;
        const int row0 = (w & 255) * 64;
        const int cnt = g_cnt[e];
        const int n0 = nblk * 128;
        const int base = g_base[e];

        if (tid == 0) {
            while (atomicAdd(&g_w12_ready[e * 32 + nblk], 0) < 8) { }
        }
        if (tid < 64) {
            int r = row0 + tid;
            if (r >= cnt) r = cnt - 1;
            toks[tid] = g_idx[e * T_TOKENS + r];
        }
        if (tid < 128) bb1[tid] = b1[e * DH + n0 + tid];
        else           bb2[tid - 128] = b2[e * DH + n0 + (tid - 128)];
        __syncthreads();

        const int arow = tid >> 2, aseg = tid & 3;
        const char* asrc = (const char*)(g_xh + (size_t)toks[arow] * DM) + aseg * 16;
        const uint32_t adst = sb + arow * 80 + aseg * 16;
        const char* bsrc = (const char*)(g_w12t + ((size_t)(e * 32 + nblk) * 64) * 512) + tid * 16;
        const uint32_t bdst = sb + FI_B + tid * 16;

        float c1[2][4][4], c2[2][4][4];
#pragma unroll
        for (int i = 0; i < 2; i++)
#pragma unroll
            for (int j = 0; j < 4; j++)
#pragma unroll
                for (int q = 0; q < 4; q++) { c1[i][j][q] = 0.0f; c2[i][j][q] = 0.0f; }

        auto stage = [&](int kt, int buf) {
            uint32_t o = buf * FI_STAGE;
            cp16(adst + o, asrc + (size_t)kt * 64);
            cp16(bdst + o, bsrc + (size_t)kt * 16384);
            cp16(bdst + o + 4096, bsrc + (size_t)kt * 16384 + 4096);
            cp16(bdst + o + 8192, bsrc + (size_t)kt * 16384 + 8192);
            cp16(bdst + o + 12288, bsrc + (size_t)kt * 16384 + 12288);
        };

#pragma unroll
        for (int i = 0; i < 4; i++) { stage(i, i); cp_commit(); }

        int ld_buf = 4, rd_buf = 0;
        for (int kt = 0; kt < 32; kt++) {
            cp_wait3();
            __syncthreads();
            const uint32_t so = rd_buf * FI_STAGE;
            rd_buf = (rd_buf == FI_NS - 1) ? 0 : rd_buf + 1;

            uint32_t a0[2][4];
#pragma unroll
            for (int im = 0; im < 2; im++)
                ldm4(a0[im], sb + so + (wm + im * 16 + lrow) * 80 + lhalf * 16);
            if (kt + 4 < 32) stage(kt + 4, ld_buf);
            cp_commit();
            ld_buf = (ld_buf == FI_NS - 1) ? 0 : ld_buf + 1;

#pragma unroll
            for (int jn = 0; jn < 4; jn++) {
                const char* bp = smem + so + FI_B + ((((wn >> 3) + jn) * 32 + lane) << 4);
                uint4 v = *(const uint4*)bp;
                mma16(c1[0][jn], a0[0], v.x, v.y);
                mma16(c1[1][jn], a0[1], v.x, v.y);
                mma16(c2[0][jn], a0[0], v.z, v.w);
                mma16(c2[1][jn], a0[1], v.z, v.w);
            }
            uint32_t a1[2][4];
#pragma unroll
            for (int im = 0; im < 2; im++)
                ldm4(a1[im], sb + so + (wm + im * 16 + lrow) * 80 + 32 + lhalf * 16);
#pragma unroll
            for (int jn = 0; jn < 4; jn++) {
                const char* bp = smem + so + FI_B + 8192 + ((((wn >> 3) + jn) * 32 + lane) << 4);
                uint4 v = *(const uint4*)bp;
                mma16(c1[0][jn], a1[0], v.x, v.y);
                mma16(c1[1][jn], a1[1], v.x, v.y);
                mma16(c2[0][jn], a1[0], v.z, v.w);
                mma16(c2[1][jn], a1[1], v.z, v.w);
            }
        }

#pragma unroll
        for (int im = 0; im < 2; im++) {
#pragma unroll
            for (int jn = 0; jn < 4; jn++) {
                int colL = wn + jn * 8 + 2 * tg;
                float bv1a = bb1[colL], bv1b = bb1[colL + 1];
                float bv2a = bb2[colL], bv2b = bb2[colL + 1];
                int r0 = row0 + wm + im * 16 + g;
                size_t colG = (size_t)n0 + colL;
                if (r0 < cnt) {
                    float v1 = c1[im][jn][0] + bv1a, ww = c2[im][jn][0] + bv2a;
                    float h0 = v1 * ww / (1.0f + __expf(-ww));
                    v1 = c1[im][jn][1] + bv1b; ww = c2[im][jn][1] + bv2b;
                    float h1 = v1 * ww / (1.0f + __expf(-ww));
                    *(uint32_t*)(g_Hh + (size_t)(base + r0) * DH + colG) = pk(h0, h1);
                }
                int r1 = r0 + 8;
                if (r1 < cnt) {
                    float v1 = c1[im][jn][2] + bv1a, ww = c2[im][jn][2] + bv2a;
                    float h0 = v1 * ww / (1.0f + __expf(-ww));
                    v1 = c1[im][jn][3] + bv1b; ww = c2[im][jn][3] + bv2b;
                    float h1 = v1 * ww / (1.0f + __expf(-ww));
                    *(uint32_t*)(g_Hh + (size_t)(base + r1) * DH + colG) = pk(h0, h1);
                }
            }
        }
        __syncthreads();
    }
}

// ---------------- FFN-out (persistent, 64x128 tiles, 3 CTAs/SM, NS=5) ---------
#define FO_STAGE 13312
#define FO_NS 5
#define FO_B 5120
#define FO_BB (FO_NS * FO_STAGE)
#define FO_TILE (FO_BB + 512)
#define FO_SMEM (FO_TILE + 16)

__global__ __launch_bounds__(256, 3) void ffn_out_h(const float* __restrict__ bo) {
    extern __shared__ __align__(16) char smem[];
    const uint32_t sb = smem_u32(smem);
    const int tid = threadIdx.x;
    const int lane = tid & 31, wid = tid >> 5;
    const int wm = (wid & 1) * 32, wn = (wid >> 1) * 32;
    const int g = lane >> 2, tg = lane & 3;
    const uint32_t lrow = lane & 15, lhalf = lane >> 4;
    int* s_tile = (int*)(smem + FO_TILE);
    float* bb = (float*)(smem + FO_BB);

    while (true) {
        if (tid == 0) *s_tile = atomicAdd(&g_tick_out, 1);
        __syncthreads();
        const int t = *s_tile;
        if (t >= g_ntiles_out) break;
        const int w = g_tiles_out[t];
        const int e = w >> 16, nblk = (w >> 8) & 255;
        const int row0 = (w & 255) * 64;
        const int cnt = g_cnt[e];
        const int n0 = nblk * 128;
        const int base = g_base[e];

        if (tid < 128) bb[tid] = bo[e * DM + n0 + tid];
        __syncthreads();

        const int arow = tid >> 2, aseg = tid & 3;
        int ar = row0 + arow;
        if (ar >= cnt) ar = cnt - 1;
        const char* asrc = (const char*)(g_Hh + (size_t)(base + ar) * DH) + aseg * 16;
        const uint32_t adst = sb + arow * 80 + aseg * 16;
        const char* bsrc = (const char*)g_wot + (size_t)(e * 8 + nblk) * 256 * 4096 + tid * 16;
        const uint32_t bdst = sb + FO_B + tid * 16;

        float c[2][4][4];
#pragma unroll
        for (int i = 0; i < 2; i++)
#pragma unroll
            for (int j = 0; j < 4; j++)
#pragma unroll
                for (int q = 0; q < 4; q++) c[i][j][q] = 0.0f;

        auto stage = [&](int kt, int buf) {
            uint32_t o = buf * FO_STAGE;
            cp16(adst + o, asrc + (size_t)kt * 64);
            cp16(bdst + o, bsrc + (size_t)kt * 8192);
            cp16(bdst + o + 4096, bsrc + (size_t)kt * 8192 + 4096);
        };

#pragma unroll
        for (int i = 0; i < 4; i++) { stage(i, i); cp_commit(); }

        int ld_buf = 4, rd_buf = 0;
        for (int kt = 0; kt < 128; kt++) {
            cp_wait3();
            __syncthreads();
            const uint32_t so = rd_buf * FO_STAGE;
            rd_buf = (rd_buf == FO_NS - 1) ? 0 : rd_buf + 1;

            uint32_t a0[2][4];
#pragma unroll
            for (int im = 0; im < 2; im++)
                ldm4(a0[im], sb + so + (wm + im * 16 + lrow) * 80 + lhalf * 16);
            if (kt + 4 < 128) stage(kt + 4, ld_buf);
            cp_commit();
            ld_buf = (ld_buf == FO_NS - 1) ? 0 : ld_buf + 1;

#pragma unroll
            for (int jn = 0; jn < 4; jn++) {
                const char* bp = smem + so + FO_B + ((((wn >> 3) + jn) * 32 + lane) << 3);
                uint2 v = *(const uint2*)bp;
                mma16(c[0][jn], a0[0], v.x, v.y);
                mma16(c[1][jn], a0[1], v.x, v.y);
            }
            uint32_t a1[2][4];
#pragma unroll
            for (int im = 0; im < 2; im++)
                ldm4(a1[im], sb + so + (wm + im * 16 + lrow) * 80 + 32 + lhalf * 16);
#pragma unroll
            for (int jn = 0; jn < 4; jn++) {
                const char* bp = smem + so + FO_B + 4096 + ((((wn >> 3) + jn) * 32 + lane) << 3);
                uint2 v = *(const uint2*)bp;
                mma16(c[0][jn], a1[0], v.x, v.y);
                mma16(c[1][jn], a1[1], v.x, v.y);
            }
        }

#pragma unroll
        for (int im = 0; im < 2; im++) {
#pragma unroll
            for (int jn = 0; jn < 4; jn++) {
                int colL = wn + jn * 8 + 2 * tg;
                float ba = bb[colL], bbv = bb[colL + 1];
                int r0 = row0 + wm + im * 16 + g;
                size_t colG = (size_t)n0 + colL;
                if (r0 < cnt) {
                    float2 o;
                    o.x = c[im][jn][0] + ba;
                    o.y = c[im][jn][1] + bbv;
                    *(float2*)(g_Y + (size_t)(base + r0) * DM + colG) = o;
                }
                int r1 = r0 + 8;
                if (r1 < cnt) {
                    float2 o;
                    o.x = c[im][jn][2] + ba;
                    o.y = c[im][jn][3] + bbv;
                    *(float2*)(g_Y + (size_t)(base + r1) * DM + colG) = o;
                }
            }
        }
    }
}

// ---------------- combine ------------------------------------------------------
__global__ void combine_kernel(float* __restrict__ out) {
    int t = blockIdx.x;
    int tid = threadIdx.x;
    int e1 = g_tok_e[2 * t], e2 = g_tok_e[2 * t + 1];
    float w1v = g_tok_w[2 * t], w2v = g_tok_w[2 * t + 1];
    size_t r1 = (size_t)(g_base[e1] + g_tok_slot[2 * t]) * DM;
    size_t r2 = (size_t)(g_base[e2] + g_tok_slot[2 * t + 1]) * DM;
    float4 a = ((const float4*)(g_Y + r1))[tid];
    float4 b = ((const float4*)(g_Y + r2))[tid];
    float4 o;
    o.x = w1v * a.x + w2v * b.x;
    o.y = w1v * a.y + w2v * b.y;
    o.z = w1v * a.z + w2v * b.z;
    o.w = w1v * a.w + w2v * b.w;
    ((float4*)(out + (size_t)t * DM))[tid] = o;
}

// ---------------- launch -------------------------------------------------------
extern "C" void kernel_launch(void* const* d_in, const int* in_sizes, int n_in,
                              void* d_out, int out_size) {
    (void)in_sizes; (void)n_in; (void)out_size;
    const float* x  = (const float*)d_in[0];
    const float* rw = (const float*)d_in[1];
    const float* rb = (const float*)d_in[2];
    const float* w1 = (const float*)d_in[3];
    const float* b1 = (const float*)d_in[4];
    const float* w2 = (const float*)d_in[5];
    const float* b2 = (const float*)d_in[6];
    const float* wo = (const float*)d_in[7];
    const float* bo = (const float*)d_in[8];
    float* out = (float*)d_out;

    static bool once = false;
    if (!once) {
        cudaFuncSetAttribute(ffn_in_h, cudaFuncAttributeMaxDynamicSharedMemorySize, FI_SMEM);
        cudaFuncSetAttribute(ffn_out_h, cudaFuncAttributeMaxDynamicSharedMemorySize, FO_SMEM);
        once = true;
    }

    init_kernel<<<1, 256>>>();
    router_prep<<<T_TOKENS / 8, 256>>>(x, rw, rb);
    ffn_in_h<<<304, 256, FI_SMEM>>>(b1, b2, w1, w2, wo, out);
    ffn_out_h<<<456, 256, FO_SMEM>>>(bo);
    combine_kernel<<<T_TOKENS, 256>>>(out);
}

// round 17
// speedup vs baseline: 1.0332x; 1.0332x over previous
#include <cuda_runtime.h>
#include <cuda_fp16.h>
#include <cstdint>

#define T_TOKENS 4096
#define DM 1024
#define DH 4096
#define NE 8
#define NW 2048   // wo-prep work items folded into ffn_in queue

// ---------------- scratch (device globals) -----------------------------------
__device__ int   g_cnt[NE];
__device__ int   g_base[NE];
__device__ float g_probsum[NE];
__device__ int   g_idx[NE * T_TOKENS];
__device__ int   g_tok_e[T_TOKENS * 2];
__device__ int   g_tok_slot[T_TOKENS * 2];
__device__ float g_tok_w[T_TOKENS * 2];
__device__ __half g_xh[(size_t)T_TOKENS * DM];
__device__ __half g_Hh[(size_t)2 * T_TOKENS * DH];
__device__ float  g_Y[(size_t)2 * T_TOKENS * DM];
__device__ uint4  g_w12t[(size_t)NE * 32 * 64 * 512];
__device__ uint2  g_wot[(size_t)NE * 8 * 256 * 512];
// persistent-queue state
__device__ int g_tiles_in[6144];
__device__ int g_tiles_out[2048];
__device__ int g_ntiles_in, g_ntiles_out;
__device__ int g_tick_in, g_tick_out;
__device__ int g_ready;

// ---------------- helpers -----------------------------------------------------
__device__ __forceinline__ uint32_t smem_u32(const void* p) {
    uint32_t a;
    asm("{ .reg .u64 t; cvta.to.shared.u64 t, %1; cvt.u32.u64 %0, t; }" : "=r"(a) : "l"(p));
    return a;
}
__device__ __forceinline__ uint32_t pk(float lo, float hi) {
    __half2 h = __floats2half2_rn(lo, hi);
    return *(uint32_t*)&h;
}
__device__ __forceinline__ void cp16(uint32_t dst, const void* src) {
    asm volatile("cp.async.cg.shared.global [%0], [%1], 16;" :: "r"(dst), "l"(src) : "memory");
}
__device__ __forceinline__ void cp_commit() {
    asm volatile("cp.async.commit_group;" ::: "memory");
}
__device__ __forceinline__ void cp_wait3() {
    asm volatile("cp.async.wait_group 3;" ::: "memory");
}
__device__ __forceinline__ void ldm4(uint32_t a[4], uint32_t addr) {
    asm volatile("ldmatrix.sync.aligned.m8n8.x4.shared.b16 {%0,%1,%2,%3}, [%4];"
                 : "=r"(a[0]), "=r"(a[1]), "=r"(a[2]), "=r"(a[3]) : "r"(addr));
}
__device__ __forceinline__ void mma16(float c[4], const uint32_t a[4],
                                      uint32_t b0, uint32_t b1) {
    asm volatile("mma.sync.aligned.m16n8k16.row.col.f32.f16.f16.f32 "
                 "{%0,%1,%2,%3}, {%4,%5,%6,%7}, {%8,%9}, {%0,%1,%2,%3};"
                 : "+f"(c[0]), "+f"(c[1]), "+f"(c[2]), "+f"(c[3])
                 : "r"(a[0]), "r"(a[1]), "r"(a[2]), "r"(a[3]), "r"(b0), "r"(b1));
}

// ---------------- init --------------------------------------------------------
__global__ void init_kernel() {
    int i = threadIdx.x;
    if (i < NE) { g_cnt[i] = 0; g_probsum[i] = 0.0f; }
    if (i == 0) { g_tick_in = 0; g_tick_out = 0; g_ready = 0; }
}

// ---------------- fused router + x fp16 conversion ----------------------------
__global__ __launch_bounds__(256) void router_prep(
    const float* __restrict__ x, const float* __restrict__ rw, const float* __restrict__ rb)
{
    __shared__ float s_rwT[NE * DM];
    const int tid = threadIdx.x;
    for (int i = tid; i < NE * DM; i += 256) {
        int k = i >> 3, e = i & 7;
        s_rwT[e * DM + k] = rw[i];
    }
    __syncthreads();

    const int lane = tid & 31, wid = tid >> 5;
    const int t = blockIdx.x * 8 + wid;
    const float4* xr = (const float4*)(x + (size_t)t * DM);

    float acc[NE];
#pragma unroll
    for (int e = 0; e < NE; e++) acc[e] = 0.0f;

#pragma unroll
    for (int it = 0; it < 8; it++) {
        const int k4 = it * 32 + lane;
        float4 v = xr[k4];
        uint2 o;
        o.x = pk(v.x, v.y);
        o.y = pk(v.z, v.w);
        *(uint2*)(g_xh + (size_t)t * DM + k4 * 4) = o;
#pragma unroll
        for (int e = 0; e < NE; e++) {
            float4 r = *(const float4*)(s_rwT + e * DM + k4 * 4);
            acc[e] += v.x * r.x + v.y * r.y + v.z * r.z + v.w * r.w;
        }
    }
#pragma unroll
    for (int e = 0; e < NE; e++)
#pragma unroll
        for (int off = 16; off > 0; off >>= 1)
            acc[e] += __shfl_xor_sync(0xffffffffu, acc[e], off);

    if (lane == 0) {
        float l[NE], p[NE];
        float m = -1e30f;
#pragma unroll
        for (int e = 0; e < NE; e++) { l[e] = acc[e] + rb[e]; m = fmaxf(m, l[e]); }
        float s = 0.0f;
#pragma unroll
        for (int e = 0; e < NE; e++) { p[e] = expf(l[e] - m); s += p[e]; }
        float inv = 1.0f / s;
#pragma unroll
        for (int e = 0; e < NE; e++) { p[e] *= inv; atomicAdd(&g_probsum[e], p[e]); }
        int i1 = 0; float p1 = p[0];
        int i2 = -1; float p2 = -1.0f;
#pragma unroll
        for (int e = 1; e < NE; e++) {
            if (p[e] > p1) { p2 = p1; i2 = i1; p1 = p[e]; i1 = e; }
            else if (p[e] > p2) { p2 = p[e]; i2 = e; }
        }
        int s1 = atomicAdd(&g_cnt[i1], 1);
        g_idx[i1 * T_TOKENS + s1] = t;
        int s2 = atomicAdd(&g_cnt[i2], 1);
        g_idx[i2 * T_TOKENS + s2] = t;
        g_tok_e[2 * t + 0] = i1; g_tok_slot[2 * t + 0] = s1; g_tok_w[2 * t + 0] = p1;
        g_tok_e[2 * t + 1] = i2; g_tok_slot[2 * t + 1] = s2; g_tok_w[2 * t + 1] = p2;
    }
}

// ---------------- weight prep (w1/w2 only; wo folded into ffn_in) --------------
__global__ __launch_bounds__(256) void prep_w12(
    const float* __restrict__ w1, const float* __restrict__ w2)
{
    const int kb = blockIdx.x, nblk = blockIdx.y, e = blockIdx.z;
    __shared__ float s1[16][132], s2[16][132];
    const float* w1e = w1 + (size_t)e * DM * DH + (size_t)(kb * 16) * DH + nblk * 128;
    const float* w2e = w2 + (size_t)e * DM * DH + (size_t)(kb * 16) * DH + nblk * 128;
    const int tid = threadIdx.x;
#pragma unroll
    for (int r = 0; r < 2; r++) {
        int t2 = tid + r * 256;
        int k = t2 >> 5, n4 = (t2 & 31) * 4;
        float4 v = *(const float4*)(w1e + (size_t)k * DH + n4);
        s1[k][n4] = v.x; s1[k][n4 + 1] = v.y; s1[k][n4 + 2] = v.z; s1[k][n4 + 3] = v.w;
        v = *(const float4*)(w2e + (size_t)k * DH + n4);
        s2[k][n4] = v.x; s2[k][n4 + 1] = v.y; s2[k][n4 + 2] = v.z; s2[k][n4 + 3] = v.w;
    }
    __syncthreads();
    uint4* dst = g_w12t + ((size_t)((e * 32 + nblk) * 64 + kb)) * 512;
#pragma unroll
    for (int r = 0; r < 2; r++) {
        int slot = tid + r * 256;
        int lane = slot & 31, jn8 = slot >> 5;
        int col = jn8 * 8 + (lane >> 2);
        int k2 = (lane & 3) * 2;
        uint4 o;
        o.x = pk(s1[k2][col], s1[k2 + 1][col]);
        o.y = pk(s1[k2 + 8][col], s1[k2 + 9][col]);
        o.z = pk(s2[k2][col], s2[k2 + 1][col]);
        o.w = pk(s2[k2 + 8][col], s2[k2 + 9][col]);
        dst[slot] = o;
    }
}

// ---------------- FFN-in (persistent; GEMM tiles + folded wo-prep items) -------
#define FI_STAGE 21504
#define FI_NS 5
#define FI_B 5120
#define FI_TOK (FI_NS * FI_STAGE)
#define FI_BB1 (FI_TOK + 256)
#define FI_BB2 (FI_BB1 + 512)
#define FI_TILE (FI_BB2 + 512)
#define FI_SMEM (FI_TILE + 160)

__global__ __launch_bounds__(256, 2) void ffn_in_h(
    const float* __restrict__ b1, const float* __restrict__ b2,
    const float* __restrict__ wo, float* __restrict__ out)
{
    extern __shared__ __align__(16) char smem[];
    const uint32_t sb = smem_u32(smem);
    const int tid = threadIdx.x;
    const int lane = tid & 31, wid = tid >> 5;
    const int wm = (wid & 1) * 32, wn = (wid >> 1) * 32;
    const int g = lane >> 2, tg = lane & 3;
    const uint32_t lrow = lane & 15, lhalf = lane >> 4;
    int* s_tile = (int*)(smem + FI_TILE);
    int* toks = (int*)(smem + FI_TOK);
    float* bb1 = (float*)(smem + FI_BB1);
    float* bb2 = (float*)(smem + FI_BB2);
    float* sconv = (float*)smem;          // 16x132 f32 scratch for wo-prep

    // ---- finalize phase: CTA0 builds scan + tile lists ----
    bool ready_seen = false;
    if (blockIdx.x == 0) {
        int* s_rb = s_tile + 2;
        int* s_ti = s_rb + NE;
        int* s_to = s_ti + NE + 1;
        if (tid == 0) {
            int base = 0, ti = 0, to = 0;
            float lb = 0.0f;
            for (int e = 0; e < NE; e++) {
                g_base[e] = base;
                base += g_cnt[e];
                lb += ((float)g_cnt[e] / T_TOKENS) * (g_probsum[e] / T_TOKENS);
                int rb = (g_cnt[e] + 63) >> 6;
                s_rb[e] = rb;
                s_ti[e] = ti; s_to[e] = to;
                ti += rb * 32;
                to += rb * 8;
            }
            s_ti[NE] = ti; s_to[NE] = to;
            g_ntiles_in = ti; g_ntiles_out = to;
            out[(size_t)T_TOKENS * DM] = 0.01f * (float)NE * lb;
        }
        __syncthreads();
        const int nti = s_ti[NE], nto = s_to[NE];
        for (int i = tid; i < nti; i += 256) {
            int e = 0;
            while (i >= s_ti[e + 1]) e++;
            int loc = i - s_ti[e];
            int rb = s_rb[e];
            int nblk = loc / rb, r = loc - nblk * rb;
            g_tiles_in[i] = (e << 16) | (nblk << 8) | r;
        }
        for (int i = tid; i < nto; i += 256) {
            int e = 0;
            while (i >= s_to[e + 1]) e++;
            int loc = i - s_to[e];
            int rb = s_rb[e];
            int nblk = loc / rb, r = loc - nblk * rb;
            g_tiles_out[i] = (e << 16) | (nblk << 8) | r;
        }
        __syncthreads();
        if (tid == 0) {
            __threadfence();
            atomicExch(&g_ready, 1);
        }
        ready_seen = true;
    }

    // ---- persistent loop: items [t%3==2, t<3*NW] = wo-prep; else GEMM ----
    while (true) {
        if (tid == 0) *s_tile = atomicAdd(&g_tick_in, 1);
        __syncthreads();
        const int t = *s_tile;
        int is_wo, idx;
        if (t < 3 * NW) {
            if (t % 3 == 2) { is_wo = 1; idx = t / 3; }
            else            { is_wo = 0; idx = (t / 3) * 2 + (t % 3); }
        } else {
            is_wo = 0; idx = t - NW;
        }

        if (is_wo) {
            const int e = idx >> 8;
            const int nblk = (idx >> 5) & 7;
            const int kb0 = (idx & 31) * 8;
#pragma unroll 1
            for (int j = 0; j < 8; j++) {
                const int kb = kb0 + j;
                const float* we = wo + (size_t)e * DH * DM + (size_t)(kb * 16) * DM + nblk * 128;
#pragma unroll
                for (int r = 0; r < 2; r++) {
                    int t2 = tid + r * 256;
                    int k = t2 >> 5, n4 = (t2 & 31) * 4;
                    float4 v = *(const float4*)(we + (size_t)k * DM + n4);
                    sconv[k * 132 + n4] = v.x; sconv[k * 132 + n4 + 1] = v.y;
                    sconv[k * 132 + n4 + 2] = v.z; sconv[k * 132 + n4 + 3] = v.w;
                }
                __syncthreads();
                uint2* dst = g_wot + ((size_t)((e * 8 + nblk) * 256 + kb)) * 512;
#pragma unroll
                for (int r = 0; r < 2; r++) {
                    int slot = tid + r * 256;
                    int ln = slot & 31, jn8 = slot >> 5;
                    int col = jn8 * 8 + (ln >> 2);
                    int k2 = (ln & 3) * 2;
                    uint2 o;
                    o.x = pk(sconv[k2 * 132 + col], sconv[(k2 + 1) * 132 + col]);
                    o.y = pk(sconv[(k2 + 8) * 132 + col], sconv[(k2 + 9) * 132 + col]);
                    dst[slot] = o;
                }
                __syncthreads();
            }
            continue;
        }

        // GEMM tile: requires finalize results
        if (!ready_seen) {
            if (tid == 0) {
                while (atomicAdd(&g_ready, 0) == 0) { }
            }
            __syncthreads();
            ready_seen = true;
        }
        if (idx >= g_ntiles_in) break;
        const int w = g_tiles_in[idx];
        const int e = w >> 16, nblk = (w >> 8) & 255;
        const int row0 = (w & 255) * 64;
        const int cnt = g_cnt[e];
        const int n0 = nblk * 128;
        const int base = g_base[e];

        if (tid < 64) {
            int r = row0 + tid;
            if (r >= cnt) r = cnt - 1;
            toks[tid] = g_idx[e * T_TOKENS + r];
        }
        if (tid < 128) bb1[tid] = b1[e * DH + n0 + tid];
        else           bb2[tid - 128] = b2[e * DH + n0 + (tid - 128)];
        __syncthreads();

        const int arow = tid >> 2, aseg = tid & 3;
        const char* asrc = (const char*)(g_xh + (size_t)toks[arow] * DM) + aseg * 16;
        const uint32_t adst = sb + arow * 80 + aseg * 16;
        const char* bsrc = (const char*)(g_w12t + ((size_t)(e * 32 + nblk) * 64) * 512) + tid * 16;
        const uint32_t bdst = sb + FI_B + tid * 16;

        float c1[2][4][4], c2[2][4][4];
#pragma unroll
        for (int i = 0; i < 2; i++)
#pragma unroll
            for (int j = 0; j < 4; j++)
#pragma unroll
                for (int q = 0; q < 4; q++) { c1[i][j][q] = 0.0f; c2[i][j][q] = 0.0f; }

        auto stage = [&](int kt, int buf) {
            uint32_t o = buf * FI_STAGE;
            cp16(adst + o, asrc + (size_t)kt * 64);
            cp16(bdst + o, bsrc + (size_t)kt * 16384);
            cp16(bdst + o + 4096, bsrc + (size_t)kt * 16384 + 4096);
            cp16(bdst + o + 8192, bsrc + (size_t)kt * 16384 + 8192);
            cp16(bdst + o + 12288, bsrc + (size_t)kt * 16384 + 12288);
        };

#pragma unroll
        for (int i = 0; i < 4; i++) { stage(i, i); cp_commit(); }

        int ld_buf = 4, rd_buf = 0;
        for (int kt = 0; kt < 32; kt++) {
            cp_wait3();
            __syncthreads();
            const uint32_t so = rd_buf * FI_STAGE;
            rd_buf = (rd_buf == FI_NS - 1) ? 0 : rd_buf + 1;

            uint32_t a0[2][4];
#pragma unroll
            for (int im = 0; im < 2; im++)
                ldm4(a0[im], sb + so + (wm + im * 16 + lrow) * 80 + lhalf * 16);
            if (kt + 4 < 32) stage(kt + 4, ld_buf);
            cp_commit();
            ld_buf = (ld_buf == FI_NS - 1) ? 0 : ld_buf + 1;

#pragma unroll
            for (int jn = 0; jn < 4; jn++) {
                const char* bp = smem + so + FI_B + ((((wn >> 3) + jn) * 32 + lane) << 4);
                uint4 v = *(const uint4*)bp;
                mma16(c1[0][jn], a0[0], v.x, v.y);
                mma16(c1[1][jn], a0[1], v.x, v.y);
                mma16(c2[0][jn], a0[0], v.z, v.w);
                mma16(c2[1][jn], a0[1], v.z, v.w);
            }
            uint32_t a1[2][4];
#pragma unroll
            for (int im = 0; im < 2; im++)
                ldm4(a1[im], sb + so + (wm + im * 16 + lrow) * 80 + 32 + lhalf * 16);
#pragma unroll
            for (int jn = 0; jn < 4; jn++) {
                const char* bp = smem + so + FI_B + 8192 + ((((wn >> 3) + jn) * 32 + lane) << 4);
                uint4 v = *(const uint4*)bp;
                mma16(c1[0][jn], a1[0], v.x, v.y);
                mma16(c1[1][jn], a1[1], v.x, v.y);
                mma16(c2[0][jn], a1[0], v.z, v.w);
                mma16(c2[1][jn], a1[1], v.z, v.w);
            }
        }

#pragma unroll
        for (int im = 0; im < 2; im++) {
#pragma unroll
            for (int jn = 0; jn < 4; jn++) {
                int colL = wn + jn * 8 + 2 * tg;
                float bv1a = bb1[colL], bv1b = bb1[colL + 1];
                float bv2a = bb2[colL], bv2b = bb2[colL + 1];
                int r0 = row0 + wm + im * 16 + g;
                size_t colG = (size_t)n0 + colL;
                if (r0 < cnt) {
                    float v1 = c1[im][jn][0] + bv1a, ww = c2[im][jn][0] + bv2a;
                    float h0 = v1 * ww / (1.0f + __expf(-ww));
                    v1 = c1[im][jn][1] + bv1b; ww = c2[im][jn][1] + bv2b;
                    float h1 = v1 * ww / (1.0f + __expf(-ww));
                    *(uint32_t*)(g_Hh + (size_t)(base + r0) * DH + colG) = pk(h0, h1);
                }
                int r1 = r0 + 8;
                if (r1 < cnt) {
                    float v1 = c1[im][jn][2] + bv1a, ww = c2[im][jn][2] + bv2a;
                    float h0 = v1 * ww / (1.0f + __expf(-ww));
                    v1 = c1[im][jn][3] + bv1b; ww = c2[im][jn][3] + bv2b;
                    float h1 = v1 * ww / (1.0f + __expf(-ww));
                    *(uint32_t*)(g_Hh + (size_t)(base + r1) * DH + colG) = pk(h0, h1);
                }
            }
        }
        __syncthreads();
    }
}

// ---------------- FFN-out (persistent, 64x128 tiles, 3 CTAs/SM, NS=5) ---------
#define FO_STAGE 13312
#define FO_NS 5
#define FO_B 5120
#define FO_BB (FO_NS * FO_STAGE)
#define FO_TILE (FO_BB + 512)
#define FO_SMEM (FO_TILE + 16)

__global__ __launch_bounds__(256, 3) void ffn_out_h(const float* __restrict__ bo) {
    extern __shared__ __align__(16) char smem[];
    const uint32_t sb = smem_u32(smem);
    const int tid = threadIdx.x;
    const int lane = tid & 31, wid = tid >> 5;
    const int wm = (wid & 1) * 32, wn = (wid >> 1) * 32;
    const int g = lane >> 2, tg = lane & 3;
    const uint32_t lrow = lane & 15, lhalf = lane >> 4;
    int* s_tile = (int*)(smem + FO_TILE);
    float* bb = (float*)(smem + FO_BB);

    while (true) {
        if (tid == 0) *s_tile = atomicAdd(&g_tick_out, 1);
        __syncthreads();
        const int t = *s_tile;
        if (t >= g_ntiles_out) break;
        const int w = g_tiles_out[t];
        const int e = w >> 16, nblk = (w >> 8) & 255;
        const int row0 = (w & 255) * 64;
        const int cnt = g_cnt[e];
        const int n0 = nblk * 128;
        const int base = g_base[e];

        if (tid < 128) bb[tid] = bo[e * DM + n0 + tid];
        __syncthreads();

        const int arow = tid >> 2, aseg = tid & 3;
        int ar = row0 + arow;
        if (ar >= cnt) ar = cnt - 1;
        const char* asrc = (const char*)(g_Hh + (size_t)(base + ar) * DH) + aseg * 16;
        const uint32_t adst = sb + arow * 80 + aseg * 16;
        const char* bsrc = (const char*)g_wot + (size_t)(e * 8 + nblk) * 256 * 4096 + tid * 16;
        const uint32_t bdst = sb + FO_B + tid * 16;

        float c[2][4][4];
#pragma unroll
        for (int i = 0; i < 2; i++)
#pragma unroll
            for (int j = 0; j < 4; j++)
#pragma unroll
                for (int q = 0; q < 4; q++) c[i][j][q] = 0.0f;

        auto stage = [&](int kt, int buf) {
            uint32_t o = buf * FO_STAGE;
            cp16(adst + o, asrc + (size_t)kt * 64);
            cp16(bdst + o, bsrc + (size_t)kt * 8192);
            cp16(bdst + o + 4096, bsrc + (size_t)kt * 8192 + 4096);
        };

#pragma unroll
        for (int i = 0; i < 4; i++) { stage(i, i); cp_commit(); }

        int ld_buf = 4, rd_buf = 0;
        for (int kt = 0; kt < 128; kt++) {
            cp_wait3();
            __syncthreads();
            const uint32_t so = rd_buf * FO_STAGE;
            rd_buf = (rd_buf == FO_NS - 1) ? 0 : rd_buf + 1;

            uint32_t a0[2][4];
#pragma unroll
            for (int im = 0; im < 2; im++)
                ldm4(a0[im], sb + so + (wm + im * 16 + lrow) * 80 + lhalf * 16);
            if (kt + 4 < 128) stage(kt + 4, ld_buf);
            cp_commit();
            ld_buf = (ld_buf == FO_NS - 1) ? 0 : ld_buf + 1;

#pragma unroll
            for (int jn = 0; jn < 4; jn++) {
                const char* bp = smem + so + FO_B + ((((wn >> 3) + jn) * 32 + lane) << 3);
                uint2 v = *(const uint2*)bp;
                mma16(c[0][jn], a0[0], v.x, v.y);
                mma16(c[1][jn], a0[1], v.x, v.y);
            }
            uint32_t a1[2][4];
#pragma unroll
            for (int im = 0; im < 2; im++)
                ldm4(a1[im], sb + so + (wm + im * 16 + lrow) * 80 + 32 + lhalf * 16);
#pragma unroll
            for (int jn = 0; jn < 4; jn++) {
                const char* bp = smem + so + FO_B + 4096 + ((((wn >> 3) + jn) * 32 + lane) << 3);
                uint2 v = *(const uint2*)bp;
                mma16(c[0][jn], a1[0], v.x, v.y);
                mma16(c[1][jn], a1[1], v.x, v.y);
            }
        }

#pragma unroll
        for (int im = 0; im < 2; im++) {
#pragma unroll
            for (int jn = 0; jn < 4; jn++) {
                int colL = wn + jn * 8 + 2 * tg;
                float ba = bb[colL], bbv = bb[colL + 1];
                int r0 = row0 + wm + im * 16 + g;
                size_t colG = (size_t)n0 + colL;
                if (r0 < cnt) {
                    float2 o;
                    o.x = c[im][jn][0] + ba;
                    o.y = c[im][jn][1] + bbv;
                    *(float2*)(g_Y + (size_t)(base + r0) * DM + colG) = o;
                }
                int r1 = r0 + 8;
                if (r1 < cnt) {
                    float2 o;
                    o.x = c[im][jn][2] + ba;
                    o.y = c[im][jn][3] + bbv;
                    *(float2*)(g_Y + (size_t)(base + r1) * DM + colG) = o;
                }
            }
        }
    }
}

// ---------------- combine ------------------------------------------------------
__global__ void combine_kernel(float* __restrict__ out) {
    int t = blockIdx.x;
    int tid = threadIdx.x;
    int e1 = g_tok_e[2 * t], e2 = g_tok_e[2 * t + 1];
    float w1v = g_tok_w[2 * t], w2v = g_tok_w[2 * t + 1];
    size_t r1 = (size_t)(g_base[e1] + g_tok_slot[2 * t]) * DM;
    size_t r2 = (size_t)(g_base[e2] + g_tok_slot[2 * t + 1]) * DM;
    float4 a = ((const float4*)(g_Y + r1))[tid];
    float4 b = ((const float4*)(g_Y + r2))[tid];
    float4 o;
    o.x = w1v * a.x + w2v * b.x;
    o.y = w1v * a.y + w2v * b.y;
    o.z = w1v * a.z + w2v * b.z;
    o.w = w1v * a.w + w2v * b.w;
    ((float4*)(out + (size_t)t * DM))[tid] = o;
}

// ---------------- launch -------------------------------------------------------
extern "C" void kernel_launch(void* const* d_in, const int* in_sizes, int n_in,
                              void* d_out, int out_size) {
    (void)in_sizes; (void)n_in; (void)out_size;
    const float* x  = (const float*)d_in[0];
    const float* rw = (const float*)d_in[1];
    const float* rb = (const float*)d_in[2];
    const float* w1 = (const float*)d_in[3];
    const float* b1 = (const float*)d_in[4];
    const float* w2 = (const float*)d_in[5];
    const float* b2 = (const float*)d_in[6];
    const float* wo = (const float*)d_in[7];
    const float* bo = (const float*)d_in[8];
    float* out = (float*)d_out;

    static bool once = false;
    static cudaStream_t s2;
    static cudaEvent_t e0, eR;
    if (!once) {
        cudaFuncSetAttribute(ffn_in_h, cudaFuncAttributeMaxDynamicSharedMemorySize, FI_SMEM);
        cudaFuncSetAttribute(ffn_out_h, cudaFuncAttributeMaxDynamicSharedMemorySize, FO_SMEM);
        cudaStreamCreateWithFlags(&s2, cudaStreamNonBlocking);
        cudaEventCreateWithFlags(&e0, cudaEventDisableTiming);
        cudaEventCreateWithFlags(&eR, cudaEventDisableTiming);
        once = true;
    }

    // side stream: init -> router_prep (independent of prep_w12)
    cudaEventRecord(e0, 0);
    cudaStreamWaitEvent(s2, e0, 0);
    init_kernel<<<1, 32, 0, s2>>>();
    router_prep<<<T_TOKENS / 8, 256, 0, s2>>>(x, rw, rb);
    cudaEventRecord(eR, s2);

    // main stream: prep_w12 concurrent with router; ffn_in joins both
    prep_w12<<<dim3(64, 32, NE), 256>>>(w1, w2);
    cudaStreamWaitEvent(0, eR, 0);
    ffn_in_h<<<304, 256, FI_SMEM>>>(b1, b2, wo, out);
    ffn_out_h<<<456, 256, FO_SMEM>>>(bo);
    combine_kernel<<<T_TOKENS, 256>>>(out);
}